// round 2
// baseline (speedup 1.0000x reference)
#include <cuda_runtime.h>
#include <cstddef>

#define BB   64
#define TT   512
#define DD   300
#define HH   128
#define G4   512
#define HD2  256
#define LL   9
#define MTOK (TT*BB)

// ---------------- device scratch ----------------
__device__ float g_xp  [ (size_t)MTOK * 1024 ];  // pre-activations (m, dir*512+g)
__device__ float g_hbuf[ (size_t)MTOK * HD2  ];  // layer output (m, dir*128+j)
__device__ float g_wt  [ 2*2*HH*G4 ];            // [layer][dir][k][g] k-major W_hh
__device__ float g_em  [ (size_t)BB*TT*LL ];     // emissions (b,t,l)
__device__ float g_llh [ BB ];

__device__ __forceinline__ float sigf(float x) { return 1.f / (1.f + __expf(-x)); }

// ---------------- 0) W_hh -> k-major ----------------
__global__ void transpose_whh(const float* __restrict__ w0, const float* __restrict__ w1)
{
    int i = blockIdx.x * blockDim.x + threadIdx.x;
    if (i >= 2*2*HH*G4) return;
    int layer = i >> 17;
    int r     = i & 131071;
    int dirr  = r >> 16;
    int r2    = r & 65535;
    int k     = r2 >> 9;
    int g     = r2 & 511;
    const float* w = layer ? w1 : w0;
    g_wt[i] = w[dirr*65536 + g*HH + k];
}

// ---------------- 1) input-projection GEMM ----------------
// g_xp[m][n] = sum_k A[m][k]*W[n][k] + b1[n]+b2[n];  m = t*64+b
template<bool GATHER>
__global__ void __launch_bounds__(256)
gemm_inproj(const float* __restrict__ Asrc, const int* __restrict__ word,
            const float* __restrict__ W, const float* __restrict__ b1,
            const float* __restrict__ b2, int K)
{
    __shared__ float As[8][132];
    __shared__ float Bs[8][132];
    __shared__ const float* arow_s[128];
    __shared__ float bias_s[128];

    const int tid = threadIdx.x;
    const int m0 = blockIdx.x * 128, n0 = blockIdx.y * 128;

    if (tid < 128) {
        int n = n0 + tid;
        bias_s[tid] = b1[n] + b2[n];
        int m = m0 + tid;
        const float* ap;
        if (GATHER) {
            int b = m & 63, t = m >> 6;
            ap = Asrc + (size_t)word[b*TT + t] * K;
        } else {
            ap = g_hbuf + (size_t)m * K;
        }
        arow_s[tid] = ap;
    }
    __syncthreads();

    const int r  = tid >> 1;
    const int kq = (tid & 1) * 4;
    const float* arow = arow_s[r];
    const float* brow = W + (size_t)(n0 + r) * K;
    const int ty = tid >> 4, tx = tid & 15;

    float acc[8][8];
#pragma unroll
    for (int i = 0; i < 8; i++)
#pragma unroll
        for (int j = 0; j < 8; j++) acc[i][j] = 0.f;

    for (int k0 = 0; k0 < K; k0 += 8) {
        int k = k0 + kq;
        float4 av = make_float4(0.f,0.f,0.f,0.f);
        float4 bv = make_float4(0.f,0.f,0.f,0.f);
        if (k + 4 <= K) {
            av = *(const float4*)(arow + k);
            bv = *(const float4*)(brow + k);
        }
        __syncthreads();
        As[kq+0][r]=av.x; As[kq+1][r]=av.y; As[kq+2][r]=av.z; As[kq+3][r]=av.w;
        Bs[kq+0][r]=bv.x; Bs[kq+1][r]=bv.y; Bs[kq+2][r]=bv.z; Bs[kq+3][r]=bv.w;
        __syncthreads();
#pragma unroll
        for (int kk = 0; kk < 8; kk++) {
            float a[8], bb8[8];
#pragma unroll
            for (int i = 0; i < 8; i++) a[i] = As[kk][ty*8 + i];
#pragma unroll
            for (int j = 0; j < 8; j++) bb8[j] = Bs[kk][tx*8 + j];
#pragma unroll
            for (int i = 0; i < 8; i++)
#pragma unroll
                for (int j = 0; j < 8; j++) acc[i][j] = fmaf(a[i], bb8[j], acc[i][j]);
        }
    }

#pragma unroll
    for (int i = 0; i < 8; i++) {
        float* crow = g_xp + (size_t)(m0 + ty*8 + i) * 1024 + n0;
#pragma unroll
        for (int j = 0; j < 8; j++) crow[tx*8 + j] = acc[i][j] + bias_s[tx*8 + j];
    }
}

// ---------------- 2) LSTM scan ----------------
// grid 128 = (dir, b); 512 threads, thread g owns gate g (0..511).
// W_hh split: k 0..63 smem, k 64..111 registers, k 112..127 global (L1-resident).
#define SCAN_SMEM ((64*512 + 128 + 512) * 4)

__global__ void __launch_bounds__(512)
lstm_scan(int layer)
{
    extern __shared__ float sm[];
    float* w_s = sm;                 // 64*512
    float* h_s = sm + 32768;         // 128
    float* gex = sm + 32768 + 128;   // 512

    const int g   = threadIdx.x;
    const int dir = blockIdx.x >> 6;
    const int b   = blockIdx.x & 63;
    const float* pw = g_wt + (size_t)(layer*2 + dir) * 65536;

    // preload smem weights (k 0..63)
    for (int i = g; i < 32768; i += 512) w_s[i] = pw[i];
    // register weights (k 64..111)
    float wr[48];
#pragma unroll
    for (int k = 0; k < 48; k++) wr[k] = pw[(64 + k)*512 + g];
    const float* wg = pw + 112*512 + g;  // k 112..127

    if (g < 128) h_s[g] = 0.f;
    float c = 0.f;
    __syncthreads();

    const float* xp = g_xp + (size_t)(dir*512 + g);

    for (int s = 0; s < TT; s++) {
        int t = dir ? (TT - 1 - s) : s;
        int m = t*64 + b;
        float acc = xp[(size_t)m * 1024];

#pragma unroll 8
        for (int k = 0; k < 64; k += 4) {
            float4 h4 = *(const float4*)(h_s + k);
            acc = fmaf(h4.x, w_s[(k+0)*512 + g], acc);
            acc = fmaf(h4.y, w_s[(k+1)*512 + g], acc);
            acc = fmaf(h4.z, w_s[(k+2)*512 + g], acc);
            acc = fmaf(h4.w, w_s[(k+3)*512 + g], acc);
        }
#pragma unroll
        for (int k = 0; k < 48; k += 4) {
            float4 h4 = *(const float4*)(h_s + 64 + k);
            acc = fmaf(h4.x, wr[k+0], acc);
            acc = fmaf(h4.y, wr[k+1], acc);
            acc = fmaf(h4.z, wr[k+2], acc);
            acc = fmaf(h4.w, wr[k+3], acc);
        }
#pragma unroll
        for (int k = 0; k < 16; k += 4) {
            float4 h4 = *(const float4*)(h_s + 112 + k);
            acc = fmaf(h4.x, wg[(k+0)*512], acc);
            acc = fmaf(h4.y, wg[(k+1)*512], acc);
            acc = fmaf(h4.z, wg[(k+2)*512], acc);
            acc = fmaf(h4.w, wg[(k+3)*512], acc);
        }

        gex[g] = acc;
        __syncthreads();
        if (g < 128) {
            float i_ = sigf(gex[g]);
            float f_ = sigf(gex[128 + g]);
            float gg = tanhf(gex[256 + g]);
            float o_ = sigf(gex[384 + g]);
            c = f_ * c + i_ * gg;
            float h = o_ * tanhf(c);
            h_s[g] = h;
            g_hbuf[(size_t)m * 256 + dir*128 + g] = h;
        }
        __syncthreads();
    }
}

// ---------------- 3) emission ----------------
__global__ void __launch_bounds__(256)
emission(const float* __restrict__ wout, const float* __restrict__ bout)
{
    __shared__ float ws[LL*256];
    __shared__ float bs[LL];
    int tid = threadIdx.x;
    for (int i = tid; i < LL*256; i += 256) ws[i] = wout[i];
    if (tid < LL) bs[tid] = bout[tid];
    __syncthreads();

    int w = tid >> 5, lane = tid & 31;
    int m = blockIdx.x * 8 + w;
    const float* xr = g_hbuf + (size_t)m * 256;

    float acc[LL];
#pragma unroll
    for (int l = 0; l < LL; l++) acc[l] = 0.f;
#pragma unroll
    for (int q = 0; q < 8; q++) {
        float xv = xr[lane + q*32];
#pragma unroll
        for (int l = 0; l < LL; l++) acc[l] = fmaf(xv, ws[l*256 + lane + q*32], acc[l]);
    }
#pragma unroll
    for (int l = 0; l < LL; l++)
#pragma unroll
        for (int o = 16; o > 0; o >>= 1)
            acc[l] += __shfl_xor_sync(0xffffffffu, acc[l], o);

    if (lane == 0) {
        int t = m >> 6, b = m & 63;
        float* e = g_em + (size_t)b * (TT*LL) + t*LL;
#pragma unroll
        for (int l = 0; l < LL; l++) e[l] = acc[l] + bs[l];
    }
}

// ---------------- 4) CRF: one warp per sequence ----------------
__global__ void __launch_bounds__(32)
crf_kernel(const int* __restrict__ word, const int* __restrict__ label,
           const float* __restrict__ start_t, const float* __restrict__ end_t,
           const float* __restrict__ trans)
{
    int b = blockIdx.x;
    int lane = threadIdx.x;
    const float* emb_ = g_em + (size_t)b * (TT*LL);

    float tr[LL];
#pragma unroll
    for (int i = 0; i < LL; i++) tr[i] = 0.f;
    if (lane < LL)
#pragma unroll
        for (int i = 0; i < LL; i++) tr[i] = trans[i*LL + lane];

    float alpha = -1e30f;
    if (lane < LL) alpha = start_t[lane] + emb_[lane];

    for (int t = 1; t < TT; t++) {
        bool mt = word[b*TT + t] > 0;
        float emj = (lane < LL) ? emb_[t*LL + lane] : 0.f;
        float vs[LL], mx = -1e30f;
#pragma unroll
        for (int i = 0; i < LL; i++) {
            float ai = __shfl_sync(0xffffffffu, alpha, i);
            vs[i] = ai + tr[i];
            mx = fmaxf(mx, vs[i]);
        }
        float s = 0.f;
#pragma unroll
        for (int i = 0; i < LL; i++) s += __expf(vs[i] - mx);
        float nxt = mx + __logf(s) + emj;
        if (lane < LL && mt) alpha = nxt;
    }

    // denom
    float v = (lane < LL) ? alpha + end_t[lane] : -1e30f;
    float mx = v;
#pragma unroll
    for (int o = 16; o > 0; o >>= 1) mx = fmaxf(mx, __shfl_xor_sync(0xffffffffu, mx, o));
    float s = __expf(v - mx);
#pragma unroll
    for (int o = 16; o > 0; o >>= 1) s += __shfl_xor_sync(0xffffffffu, s, o);
    float denom = mx + __logf(s);

    // numerator
    float partial = 0.f;
    int cnt = 0;
    for (int t = lane; t < TT; t += 32) {
        int mt = word[b*TT + t] > 0;
        cnt += mt;
        if (t >= 1 && mt) {
            int tp = label[b*TT + t - 1];
            int tc = label[b*TT + t];
            partial += trans[tp*LL + tc] + emb_[t*LL + tc];
        }
    }
#pragma unroll
    for (int o = 16; o > 0; o >>= 1) {
        partial += __shfl_xor_sync(0xffffffffu, partial, o);
        cnt     += __shfl_xor_sync(0xffffffffu, cnt, o);
    }
    if (lane == 0) {
        int t0 = label[b*TT];
        float num = start_t[t0] + emb_[t0] + partial;
        int last = label[b*TT + cnt - 1];
        num += end_t[last];
        g_llh[b] = num - denom;
    }
}

// ---------------- 5) final reduce ----------------
__global__ void __launch_bounds__(32)
finalize(float* out)
{
    int lane = threadIdx.x;
    float v = g_llh[lane] + g_llh[lane + 32];
#pragma unroll
    for (int o = 16; o > 0; o >>= 1) v += __shfl_xor_sync(0xffffffffu, v, o);
    if (lane == 0) out[0] = -v;
}

// ---------------- host ----------------
extern "C" void kernel_launch(void* const* d_in, const int* in_sizes, int n_in,
                              void* d_out, int out_size)
{
    const int*   word    = (const int*)  d_in[0];
    const int*   label   = (const int*)  d_in[1];
    const float* emb     = (const float*)d_in[2];
    const float* w_ih_l0 = (const float*)d_in[3];
    const float* w_hh_l0 = (const float*)d_in[4];
    const float* b_ih_l0 = (const float*)d_in[5];
    const float* b_hh_l0 = (const float*)d_in[6];
    const float* w_ih_l1 = (const float*)d_in[7];
    const float* w_hh_l1 = (const float*)d_in[8];
    const float* b_ih_l1 = (const float*)d_in[9];
    const float* b_hh_l1 = (const float*)d_in[10];
    const float* w_out   = (const float*)d_in[11];
    const float* b_out   = (const float*)d_in[12];
    const float* start_t = (const float*)d_in[13];
    const float* end_t   = (const float*)d_in[14];
    const float* trans   = (const float*)d_in[15];
    float* out = (float*)d_out;

    cudaFuncSetAttribute(lstm_scan, cudaFuncAttributeMaxDynamicSharedMemorySize, SCAN_SMEM);

    transpose_whh<<<512, 512>>>(w_hh_l0, w_hh_l1);

    gemm_inproj<true ><<<dim3(256, 8), 256>>>(emb, word, w_ih_l0, b_ih_l0, b_hh_l0, DD);
    lstm_scan<<<128, 512, SCAN_SMEM>>>(0);

    gemm_inproj<false><<<dim3(256, 8), 256>>>(nullptr, word, w_ih_l1, b_ih_l1, b_hh_l1, HD2);
    lstm_scan<<<128, 512, SCAN_SMEM>>>(1);

    emission<<<MTOK/8, 256>>>(w_out, b_out);
    crf_kernel<<<BB, 32>>>(word, label, start_t, end_t, trans);
    finalize<<<1, 32>>>(out);
}

// round 3
// speedup vs baseline: 1.4538x; 1.4538x over previous
#include <cuda_runtime.h>
#include <cstddef>

#define BB   64
#define TT   512
#define DD   300
#define HH   128
#define G4   512
#define HD2  256
#define LL   9
#define MTOK (TT*BB)

// ---------------- device scratch ----------------
__device__ float g_xp  [ (size_t)MTOK * 1024 ];  // pre-activations (m, dir*512+g)
__device__ float g_hbuf[ (size_t)MTOK * HD2  ];  // layer output (m, dir*128+j)
__device__ float g_wt  [ 2*2*HH*G4 ];            // [layer][dir][k][g] k-major W_hh
__device__ float g_em  [ (size_t)BB*TT*LL ];     // emissions (b,t,l)
__device__ float g_llh [ BB ];

// ---------------- f32x2 helpers (sm_103a packed fp32) ----------------
__device__ __forceinline__ unsigned long long pack2(float lo, float hi) {
    unsigned long long r;
    asm("mov.b64 %0, {%1, %2};" : "=l"(r) : "f"(lo), "f"(hi));
    return r;
}
__device__ __forceinline__ float2 unpack2(unsigned long long v) {
    float2 f;
    asm("mov.b64 {%0, %1}, %2;" : "=f"(f.x), "=f"(f.y) : "l"(v));
    return f;
}
__device__ __forceinline__ unsigned long long ffma2(unsigned long long a,
                                                    unsigned long long b,
                                                    unsigned long long c) {
    unsigned long long d;
    asm("fma.rn.f32x2 %0, %1, %2, %3;" : "=l"(d) : "l"(a), "l"(b), "l"(c));
    return d;
}
__device__ __forceinline__ float tanh_ap(float x) {
    float y;
    asm("tanh.approx.f32 %0, %1;" : "=f"(y) : "f"(x));
    return y;
}
__device__ __forceinline__ float sig_ap(float x) {
    return fmaf(tanh_ap(0.5f * x), 0.5f, 0.5f);
}

// ---------------- 0) W_hh -> k-major ----------------
__global__ void transpose_whh(const float* __restrict__ w0, const float* __restrict__ w1)
{
    int i = blockIdx.x * blockDim.x + threadIdx.x;
    if (i >= 2*2*HH*G4) return;
    int layer = i >> 17;
    int r     = i & 131071;
    int dirr  = r >> 16;
    int r2    = r & 65535;
    int k     = r2 >> 9;
    int g     = r2 & 511;
    const float* w = layer ? w1 : w0;
    g_wt[i] = w[dirr*65536 + g*HH + k];
}

// ---------------- 1) input-projection GEMM ----------------
template<bool GATHER>
__global__ void __launch_bounds__(256)
gemm_inproj(const float* __restrict__ Asrc, const int* __restrict__ word,
            const float* __restrict__ W, const float* __restrict__ b1,
            const float* __restrict__ b2, int K)
{
    __shared__ float As[8][132];
    __shared__ float Bs[8][132];
    __shared__ const float* arow_s[128];
    __shared__ float bias_s[128];

    const int tid = threadIdx.x;
    const int m0 = blockIdx.x * 128, n0 = blockIdx.y * 128;

    if (tid < 128) {
        int n = n0 + tid;
        bias_s[tid] = b1[n] + b2[n];
        int m = m0 + tid;
        const float* ap;
        if (GATHER) {
            int b = m & 63, t = m >> 6;
            ap = Asrc + (size_t)word[b*TT + t] * K;
        } else {
            ap = g_hbuf + (size_t)m * K;
        }
        arow_s[tid] = ap;
    }
    __syncthreads();

    const int r  = tid >> 1;
    const int kq = (tid & 1) * 4;
    const float* arow = arow_s[r];
    const float* brow = W + (size_t)(n0 + r) * K;
    const int ty = tid >> 4, tx = tid & 15;

    float acc[8][8];
#pragma unroll
    for (int i = 0; i < 8; i++)
#pragma unroll
        for (int j = 0; j < 8; j++) acc[i][j] = 0.f;

    for (int k0 = 0; k0 < K; k0 += 8) {
        int k = k0 + kq;
        float4 av = make_float4(0.f,0.f,0.f,0.f);
        float4 bv = make_float4(0.f,0.f,0.f,0.f);
        if (k + 4 <= K) {
            av = *(const float4*)(arow + k);
            bv = *(const float4*)(brow + k);
        }
        __syncthreads();
        As[kq+0][r]=av.x; As[kq+1][r]=av.y; As[kq+2][r]=av.z; As[kq+3][r]=av.w;
        Bs[kq+0][r]=bv.x; Bs[kq+1][r]=bv.y; Bs[kq+2][r]=bv.z; Bs[kq+3][r]=bv.w;
        __syncthreads();
#pragma unroll
        for (int kk = 0; kk < 8; kk++) {
            float a[8], bb8[8];
#pragma unroll
            for (int i = 0; i < 8; i++) a[i] = As[kk][ty*8 + i];
#pragma unroll
            for (int j = 0; j < 8; j++) bb8[j] = Bs[kk][tx*8 + j];
#pragma unroll
            for (int i = 0; i < 8; i++)
#pragma unroll
                for (int j = 0; j < 8; j++) acc[i][j] = fmaf(a[i], bb8[j], acc[i][j]);
        }
    }

#pragma unroll
    for (int i = 0; i < 8; i++) {
        float* crow = g_xp + (size_t)(m0 + ty*8 + i) * 1024 + n0;
#pragma unroll
        for (int j = 0; j < 8; j++) crow[tx*8 + j] = acc[i][j] + bias_s[tx*8 + j];
    }
}

// ---------------- 2) LSTM scan (f32x2, register-resident weights) ----------------
// 128 CTAs = (dir, b), 512 threads; thread g owns gate g.
// k-pairs 0..47 (k=0..95) in registers; pairs 48..63 (k=96..127) in smem.
#define NREG 48
#define NSM  16
// smem: ws2 = NSM*512 ull (64KB) | h_s 128 f | gex 512 f
#define SCAN_SMEM (NSM*512*8 + 128*4 + 512*4)

__global__ void __launch_bounds__(512, 1)
lstm_scan(int layer)
{
    extern __shared__ float sm[];
    unsigned long long* ws2 = (unsigned long long*)sm;
    float* h_s = sm + NSM*512*2;
    float* gex = h_s + 128;

    const int g   = threadIdx.x;
    const int dir = blockIdx.x >> 6;
    const int b   = blockIdx.x & 63;
    const float* pw = g_wt + (size_t)(layer*2 + dir) * 65536;

    // register weights: pair j covers k=2j, 2j+1
    unsigned long long wreg[NREG];
#pragma unroll
    for (int j = 0; j < NREG; j++) {
        float lo = pw[(2*j  )*512 + g];
        float hi = pw[(2*j+1)*512 + g];
        wreg[j] = pack2(lo, hi);
    }
    // smem weights: pair j covers k = 2*NREG + 2j, +1
    for (int j = 0; j < NSM; j++) {
        float lo = pw[(2*NREG + 2*j    )*512 + g];
        float hi = pw[(2*NREG + 2*j + 1)*512 + g];
        ws2[j*512 + g] = pack2(lo, hi);
    }

    if (g < 128) h_s[g] = 0.f;
    float c = 0.f;
    __syncthreads();

    const float* xpp = g_xp + (size_t)(dir*512 + g);
    int t0 = dir ? (TT - 1) : 0;
    float xcur = xpp[(size_t)(t0*64 + b) * 1024];

    for (int s = 0; s < TT; s++) {
        int t = dir ? (TT - 1 - s) : s;
        int m = t*64 + b;

        // prefetch next step's x
        float xnext = 0.f;
        if (s + 1 < TT) {
            int tn = dir ? (t - 1) : (t + 1);
            xnext = __ldg(xpp + (size_t)(tn*64 + b) * 1024);
        }

        const unsigned long long* h2 = (const unsigned long long*)h_s;
        unsigned long long acc0 = pack2(xcur, 0.f);
        unsigned long long acc1 = pack2(0.f, 0.f);
#pragma unroll
        for (int j = 0; j < NREG; j += 2) {
            acc0 = ffma2(h2[j],     wreg[j],     acc0);
            acc1 = ffma2(h2[j + 1], wreg[j + 1], acc1);
        }
#pragma unroll
        for (int j = 0; j < NSM; j += 2) {
            acc0 = ffma2(h2[NREG + j],     ws2[(j    )*512 + g], acc0);
            acc1 = ffma2(h2[NREG + j + 1], ws2[(j + 1)*512 + g], acc1);
        }
        float2 s0 = unpack2(acc0);
        float2 s1 = unpack2(acc1);
        gex[g] = (s0.x + s1.x) + (s0.y + s1.y);
        __syncthreads();

        if (g < 128) {
            float i_ = sig_ap(gex[g]);
            float f_ = sig_ap(gex[128 + g]);
            float gg = tanh_ap(gex[256 + g]);
            float o_ = sig_ap(gex[384 + g]);
            c = fmaf(f_, c, i_ * gg);
            float h = o_ * tanh_ap(c);
            h_s[g] = h;
            g_hbuf[(size_t)m * 256 + dir*128 + g] = h;
        }
        __syncthreads();
        xcur = xnext;
    }
}

// ---------------- 3) emission ----------------
__global__ void __launch_bounds__(256)
emission(const float* __restrict__ wout, const float* __restrict__ bout)
{
    __shared__ float ws[LL*256];
    __shared__ float bs[LL];
    int tid = threadIdx.x;
    for (int i = tid; i < LL*256; i += 256) ws[i] = wout[i];
    if (tid < LL) bs[tid] = bout[tid];
    __syncthreads();

    int w = tid >> 5, lane = tid & 31;
    int m = blockIdx.x * 8 + w;
    const float* xr = g_hbuf + (size_t)m * 256;

    float acc[LL];
#pragma unroll
    for (int l = 0; l < LL; l++) acc[l] = 0.f;
#pragma unroll
    for (int q = 0; q < 8; q++) {
        float xv = xr[lane + q*32];
#pragma unroll
        for (int l = 0; l < LL; l++) acc[l] = fmaf(xv, ws[l*256 + lane + q*32], acc[l]);
    }
#pragma unroll
    for (int l = 0; l < LL; l++)
#pragma unroll
        for (int o = 16; o > 0; o >>= 1)
            acc[l] += __shfl_xor_sync(0xffffffffu, acc[l], o);

    if (lane == 0) {
        int t = m >> 6, b = m & 63;
        float* e = g_em + (size_t)b * (TT*LL) + t*LL;
#pragma unroll
        for (int l = 0; l < LL; l++) e[l] = acc[l] + bs[l];
    }
}

// ---------------- 4) CRF ----------------
__global__ void __launch_bounds__(32)
crf_kernel(const int* __restrict__ word, const int* __restrict__ label,
           const float* __restrict__ start_t, const float* __restrict__ end_t,
           const float* __restrict__ trans)
{
    int b = blockIdx.x;
    int lane = threadIdx.x;
    const float* emb_ = g_em + (size_t)b * (TT*LL);

    float tr[LL];
#pragma unroll
    for (int i = 0; i < LL; i++) tr[i] = 0.f;
    if (lane < LL)
#pragma unroll
        for (int i = 0; i < LL; i++) tr[i] = trans[i*LL + lane];

    float alpha = -1e30f;
    if (lane < LL) alpha = start_t[lane] + emb_[lane];

    for (int t = 1; t < TT; t++) {
        bool mt = word[b*TT + t] > 0;
        float emj = (lane < LL) ? emb_[t*LL + lane] : 0.f;
        float vs[LL], mx = -1e30f;
#pragma unroll
        for (int i = 0; i < LL; i++) {
            float ai = __shfl_sync(0xffffffffu, alpha, i);
            vs[i] = ai + tr[i];
            mx = fmaxf(mx, vs[i]);
        }
        float s = 0.f;
#pragma unroll
        for (int i = 0; i < LL; i++) s += __expf(vs[i] - mx);
        float nxt = mx + __logf(s) + emj;
        if (lane < LL && mt) alpha = nxt;
    }

    float v = (lane < LL) ? alpha + end_t[lane] : -1e30f;
    float mx = v;
#pragma unroll
    for (int o = 16; o > 0; o >>= 1) mx = fmaxf(mx, __shfl_xor_sync(0xffffffffu, mx, o));
    float s = __expf(v - mx);
#pragma unroll
    for (int o = 16; o > 0; o >>= 1) s += __shfl_xor_sync(0xffffffffu, s, o);
    float denom = mx + __logf(s);

    float partial = 0.f;
    int cnt = 0;
    for (int t = lane; t < TT; t += 32) {
        int mt = word[b*TT + t] > 0;
        cnt += mt;
        if (t >= 1 && mt) {
            int tp = label[b*TT + t - 1];
            int tc = label[b*TT + t];
            partial += trans[tp*LL + tc] + emb_[t*LL + tc];
        }
    }
#pragma unroll
    for (int o = 16; o > 0; o >>= 1) {
        partial += __shfl_xor_sync(0xffffffffu, partial, o);
        cnt     += __shfl_xor_sync(0xffffffffu, cnt, o);
    }
    if (lane == 0) {
        int t0 = label[b*TT];
        float num = start_t[t0] + emb_[t0] + partial;
        int last = label[b*TT + cnt - 1];
        num += end_t[last];
        g_llh[b] = num - denom;
    }
}

// ---------------- 5) final reduce ----------------
__global__ void __launch_bounds__(32)
finalize(float* out)
{
    int lane = threadIdx.x;
    float v = g_llh[lane] + g_llh[lane + 32];
#pragma unroll
    for (int o = 16; o > 0; o >>= 1) v += __shfl_xor_sync(0xffffffffu, v, o);
    if (lane == 0) out[0] = -v;
}

// ---------------- host ----------------
extern "C" void kernel_launch(void* const* d_in, const int* in_sizes, int n_in,
                              void* d_out, int out_size)
{
    const int*   word    = (const int*)  d_in[0];
    const int*   label   = (const int*)  d_in[1];
    const float* emb     = (const float*)d_in[2];
    const float* w_ih_l0 = (const float*)d_in[3];
    const float* w_hh_l0 = (const float*)d_in[4];
    const float* b_ih_l0 = (const float*)d_in[5];
    const float* b_hh_l0 = (const float*)d_in[6];
    const float* w_ih_l1 = (const float*)d_in[7];
    const float* w_hh_l1 = (const float*)d_in[8];
    const float* b_ih_l1 = (const float*)d_in[9];
    const float* b_hh_l1 = (const float*)d_in[10];
    const float* w_out   = (const float*)d_in[11];
    const float* b_out   = (const float*)d_in[12];
    const float* start_t = (const float*)d_in[13];
    const float* end_t   = (const float*)d_in[14];
    const float* trans   = (const float*)d_in[15];
    float* out = (float*)d_out;

    cudaFuncSetAttribute(lstm_scan, cudaFuncAttributeMaxDynamicSharedMemorySize, SCAN_SMEM);

    transpose_whh<<<512, 512>>>(w_hh_l0, w_hh_l1);

    gemm_inproj<true ><<<dim3(256, 8), 256>>>(emb, word, w_ih_l0, b_ih_l0, b_hh_l0, DD);
    lstm_scan<<<128, 512, SCAN_SMEM>>>(0);

    gemm_inproj<false><<<dim3(256, 8), 256>>>(nullptr, word, w_ih_l1, b_ih_l1, b_hh_l1, HD2);
    lstm_scan<<<128, 512, SCAN_SMEM>>>(1);

    emission<<<MTOK/8, 256>>>(w_out, b_out);
    crf_kernel<<<BB, 32>>>(word, label, start_t, end_t, trans);
    finalize<<<1, 32>>>(out);
}

// round 4
// speedup vs baseline: 1.9369x; 1.3323x over previous
#include <cuda_runtime.h>
#include <cstddef>
#include <cstdint>

#define BB   64
#define TT   512
#define DD   300
#define HH   128
#define G4   512
#define HD2  256
#define LL   9
#define MTOK (TT*BB)

// ---------------- device scratch ----------------
__device__ float g_xp  [ (size_t)MTOK * 1024 ];  // pre-activations (m, dir*512+g)
__device__ float g_hbuf[ (size_t)MTOK * HD2  ];  // layer output (m, dir*128+j)
__device__ float g_wt  [ 2*2*HH*G4 ];            // [layer][dir][k][g] k-major W_hh
__device__ float g_em  [ (size_t)BB*TT*LL ];     // emissions (b,t,l)
__device__ float g_llh [ BB ];

// ---------------- intrinsics ----------------
__device__ __forceinline__ unsigned long long pack2(float lo, float hi) {
    unsigned long long r;
    asm("mov.b64 %0, {%1, %2};" : "=l"(r) : "f"(lo), "f"(hi));
    return r;
}
__device__ __forceinline__ float2 unpack2(unsigned long long v) {
    float2 f;
    asm("mov.b64 {%0, %1}, %2;" : "=f"(f.x), "=f"(f.y) : "l"(v));
    return f;
}
__device__ __forceinline__ unsigned long long ffma2(unsigned long long a,
                                                    unsigned long long b,
                                                    unsigned long long c) {
    unsigned long long d;
    asm("fma.rn.f32x2 %0, %1, %2, %3;" : "=l"(d) : "l"(a), "l"(b), "l"(c));
    return d;
}
__device__ __forceinline__ float tanh_ap(float x) {
    float y;
    asm("tanh.approx.f32 %0, %1;" : "=f"(y) : "f"(x));
    return y;
}
__device__ __forceinline__ float sig_ap(float x) {
    return fmaf(tanh_ap(0.5f * x), 0.5f, 0.5f);
}
__device__ __forceinline__ uint32_t to_tf32(float f) {
    uint32_t r;
    asm("cvt.rna.tf32.f32 %0, %1;" : "=r"(r) : "f"(f));
    return r;
}
__device__ __forceinline__ void mma_tf32(float* d, const uint32_t* a, uint32_t b0, uint32_t b1) {
    asm("mma.sync.aligned.m16n8k8.row.col.f32.tf32.tf32.f32 "
        "{%0,%1,%2,%3}, {%4,%5,%6,%7}, {%8,%9}, {%0,%1,%2,%3};"
        : "+f"(d[0]), "+f"(d[1]), "+f"(d[2]), "+f"(d[3])
        : "r"(a[0]), "r"(a[1]), "r"(a[2]), "r"(a[3]), "r"(b0), "r"(b1));
}

// ---------------- 0) W_hh -> k-major ----------------
__global__ void transpose_whh(const float* __restrict__ w0, const float* __restrict__ w1)
{
    int i = blockIdx.x * blockDim.x + threadIdx.x;
    if (i >= 2*2*HH*G4) return;
    int layer = i >> 17;
    int r     = i & 131071;
    int dirr  = r >> 16;
    int r2    = r & 65535;
    int k     = r2 >> 9;
    int g     = r2 & 511;
    const float* w = layer ? w1 : w0;
    g_wt[i] = w[dirr*65536 + g*HH + k];
}

// ---------------- 1) input-projection GEMM (tf32 mma.sync) ----------------
// g_xp[m][n] = sum_k A[m][k]*W[n][k] + b1[n]+b2[n];  m = t*64+b
// CTA tile 128x128, 8 warps in 4(m) x 2(n); warp tile 32x64 = 2 x 8 mma tiles.
template<bool GATHER>
__global__ void __launch_bounds__(256)
gemm_tf32(const float* __restrict__ Asrc, const int* __restrict__ word,
          const float* __restrict__ W, const float* __restrict__ b1,
          const float* __restrict__ b2, int K)
{
    __shared__ uint32_t As[8][132];   // [k][m] tf32 bits
    __shared__ uint32_t Bs[8][132];   // [k][n] tf32 bits
    __shared__ const float* arow_s[128];
    __shared__ float bias_s[128];

    const int tid = threadIdx.x;
    const int m0 = blockIdx.x * 128, n0 = blockIdx.y * 128;

    if (tid < 128) {
        int n = n0 + tid;
        bias_s[tid] = b1[n] + b2[n];
        int m = m0 + tid;
        const float* ap;
        if (GATHER) {
            int b = m & 63, t = m >> 6;
            ap = Asrc + (size_t)word[b*TT + t] * K;
        } else {
            ap = g_hbuf + (size_t)m * K;
        }
        arow_s[tid] = ap;
    }
    __syncthreads();

    const int r  = tid >> 1;          // row within tile (0..127)
    const int kq = (tid & 1) * 4;     // 0 or 4
    const float* arow = arow_s[r];
    const float* brow = W + (size_t)(n0 + r) * K;

    const int warp  = tid >> 5;       // 0..7
    const int lane  = tid & 31;
    const int wm    = warp >> 1;      // 0..3 (m offset 32*wm)
    const int wn    = warp & 1;       // 0..1 (n offset 64*wn)
    const int group = lane >> 2;      // 0..7
    const int tig   = lane & 3;       // 0..3

    float acc[2][8][4];
#pragma unroll
    for (int mt = 0; mt < 2; mt++)
#pragma unroll
        for (int nt = 0; nt < 8; nt++)
#pragma unroll
            for (int q = 0; q < 4; q++) acc[mt][nt][q] = 0.f;

    for (int k0 = 0; k0 < K; k0 += 8) {
        int k = k0 + kq;
        float4 av = make_float4(0.f,0.f,0.f,0.f);
        float4 bv = make_float4(0.f,0.f,0.f,0.f);
        if (k + 4 <= K) {
            av = *(const float4*)(arow + k);
            bv = *(const float4*)(brow + k);
        }
        __syncthreads();
        As[kq+0][r]=to_tf32(av.x); As[kq+1][r]=to_tf32(av.y);
        As[kq+2][r]=to_tf32(av.z); As[kq+3][r]=to_tf32(av.w);
        Bs[kq+0][r]=to_tf32(bv.x); Bs[kq+1][r]=to_tf32(bv.y);
        Bs[kq+2][r]=to_tf32(bv.z); Bs[kq+3][r]=to_tf32(bv.w);
        __syncthreads();

        uint32_t afr[2][4];
#pragma unroll
        for (int mt = 0; mt < 2; mt++) {
            int mr = wm*32 + mt*16 + group;
            afr[mt][0] = As[tig  ][mr];
            afr[mt][1] = As[tig  ][mr + 8];
            afr[mt][2] = As[tig+4][mr];
            afr[mt][3] = As[tig+4][mr + 8];
        }
#pragma unroll
        for (int nt = 0; nt < 8; nt++) {
            int nc = wn*64 + nt*8 + group;
            uint32_t bv0 = Bs[tig  ][nc];
            uint32_t bv1 = Bs[tig+4][nc];
            mma_tf32(acc[0][nt], afr[0], bv0, bv1);
            mma_tf32(acc[1][nt], afr[1], bv0, bv1);
        }
    }

#pragma unroll
    for (int mt = 0; mt < 2; mt++) {
        int row = m0 + wm*32 + mt*16 + group;
#pragma unroll
        for (int nt = 0; nt < 8; nt++) {
            int ncl = wn*64 + nt*8 + 2*tig;
            float bc0 = bias_s[ncl], bc1 = bias_s[ncl + 1];
            float* r0 = g_xp + (size_t)row * 1024 + n0 + ncl;
            float* r1 = r0 + (size_t)8 * 1024;
            r0[0] = acc[mt][nt][0] + bc0;  r0[1] = acc[mt][nt][1] + bc1;
            r1[0] = acc[mt][nt][2] + bc0;  r1[1] = acc[mt][nt][3] + bc1;
        }
    }
}

// ---------------- 2) LSTM scan (f32x2, vectorized smem) ----------------
// 128 CTAs = (dir, b), 512 threads; thread g owns gate g.
// k 0..95 in 48 register pairs; k 96..127 in smem as ulonglong2[8][512].
#define NREGP 48
#define NSMU2 8
#define SCAN_SMEM (NSMU2*512*16 + 128*4 + 512*4)

__global__ void __launch_bounds__(512, 1)
lstm_scan(int layer)
{
    extern __shared__ float sm[];
    ulonglong2* ws4 = (ulonglong2*)sm;                 // 8*512*16B = 64KB
    float* h_s = (float*)(ws4 + NSMU2*512);            // 128
    float* gex = h_s + 128;                            // 512

    const int g   = threadIdx.x;
    const int dir = blockIdx.x >> 6;
    const int b   = blockIdx.x & 63;
    const float* pw = g_wt + (size_t)(layer*2 + dir) * 65536;

    unsigned long long wreg[NREGP];
#pragma unroll
    for (int p = 0; p < NREGP; p++)
        wreg[p] = pack2(pw[(2*p)*512 + g], pw[(2*p+1)*512 + g]);

    for (int j = 0; j < NSMU2; j++) {
        int kb = 96 + 4*j;
        ulonglong2 v;
        v.x = pack2(pw[(kb  )*512 + g], pw[(kb+1)*512 + g]);
        v.y = pack2(pw[(kb+2)*512 + g], pw[(kb+3)*512 + g]);
        ws4[j*512 + g] = v;
    }

    if (g < 128) h_s[g] = 0.f;
    float c = 0.f;
    __syncthreads();

    const float* xpp = g_xp + (size_t)(dir*512 + g);
    int t0 = dir ? (TT - 1) : 0;
    float xcur = xpp[(size_t)(t0*64 + b) * 1024];

    for (int s = 0; s < TT; s++) {
        int t = dir ? (TT - 1 - s) : s;
        int m = t*64 + b;

        float xnext = 0.f;
        if (s + 1 < TT) {
            int tn = dir ? (t - 1) : (t + 1);
            xnext = __ldg(xpp + (size_t)(tn*64 + b) * 1024);
        }

        const ulonglong2* h22 = (const ulonglong2*)h_s;
        unsigned long long acc0 = pack2(xcur, 0.f);
        unsigned long long acc1 = pack2(0.f, 0.f);
#pragma unroll
        for (int j = 0; j < NREGP/2; j++) {          // pairs 0..47, k 0..95
            ulonglong2 hv = h22[j];
            acc0 = ffma2(hv.x, wreg[2*j],     acc0);
            acc1 = ffma2(hv.y, wreg[2*j + 1], acc1);
        }
#pragma unroll
        for (int j = 0; j < NSMU2; j++) {            // k 96..127
            ulonglong2 hv = h22[NREGP/2 + j];
            ulonglong2 wv = ws4[j*512 + g];
            acc0 = ffma2(hv.x, wv.x, acc0);
            acc1 = ffma2(hv.y, wv.y, acc1);
        }
        float2 s0 = unpack2(acc0);
        float2 s1 = unpack2(acc1);
        gex[g] = (s0.x + s1.x) + (s0.y + s1.y);
        __syncthreads();

        if (g < 128) {
            float i_ = sig_ap(gex[g]);
            float f_ = sig_ap(gex[128 + g]);
            float gg = tanh_ap(gex[256 + g]);
            float o_ = sig_ap(gex[384 + g]);
            c = fmaf(f_, c, i_ * gg);
            float h = o_ * tanh_ap(c);
            h_s[g] = h;
            g_hbuf[(size_t)m * 256 + dir*128 + g] = h;
        }
        __syncthreads();
        xcur = xnext;
    }
}

// ---------------- 3) emission ----------------
__global__ void __launch_bounds__(256)
emission(const float* __restrict__ wout, const float* __restrict__ bout)
{
    __shared__ float ws[LL*256];
    __shared__ float bs[LL];
    int tid = threadIdx.x;
    for (int i = tid; i < LL*256; i += 256) ws[i] = wout[i];
    if (tid < LL) bs[tid] = bout[tid];
    __syncthreads();

    int w = tid >> 5, lane = tid & 31;
    int m = blockIdx.x * 8 + w;
    const float* xr = g_hbuf + (size_t)m * 256;

    float acc[LL];
#pragma unroll
    for (int l = 0; l < LL; l++) acc[l] = 0.f;
#pragma unroll
    for (int q = 0; q < 8; q++) {
        float xv = xr[lane + q*32];
#pragma unroll
        for (int l = 0; l < LL; l++) acc[l] = fmaf(xv, ws[l*256 + lane + q*32], acc[l]);
    }
#pragma unroll
    for (int l = 0; l < LL; l++)
#pragma unroll
        for (int o = 16; o > 0; o >>= 1)
            acc[l] += __shfl_xor_sync(0xffffffffu, acc[l], o);

    if (lane == 0) {
        int t = m >> 6, b = m & 63;
        float* e = g_em + (size_t)b * (TT*LL) + t*LL;
#pragma unroll
        for (int l = 0; l < LL; l++) e[l] = acc[l] + bs[l];
    }
}

// ---------------- 4) CRF ----------------
__global__ void __launch_bounds__(32)
crf_kernel(const int* __restrict__ word, const int* __restrict__ label,
           const float* __restrict__ start_t, const float* __restrict__ end_t,
           const float* __restrict__ trans)
{
    int b = blockIdx.x;
    int lane = threadIdx.x;
    const float* emb_ = g_em + (size_t)b * (TT*LL);

    float tr[LL];
#pragma unroll
    for (int i = 0; i < LL; i++) tr[i] = 0.f;
    if (lane < LL)
#pragma unroll
        for (int i = 0; i < LL; i++) tr[i] = trans[i*LL + lane];

    float alpha = -1e30f;
    if (lane < LL) alpha = start_t[lane] + emb_[lane];

    for (int t = 1; t < TT; t++) {
        bool mt = word[b*TT + t] > 0;
        float emj = (lane < LL) ? emb_[t*LL + lane] : 0.f;
        float vs[LL], mx = -1e30f;
#pragma unroll
        for (int i = 0; i < LL; i++) {
            float ai = __shfl_sync(0xffffffffu, alpha, i);
            vs[i] = ai + tr[i];
            mx = fmaxf(mx, vs[i]);
        }
        float s = 0.f;
#pragma unroll
        for (int i = 0; i < LL; i++) s += __expf(vs[i] - mx);
        float nxt = mx + __logf(s) + emj;
        if (lane < LL && mt) alpha = nxt;
    }

    float v = (lane < LL) ? alpha + end_t[lane] : -1e30f;
    float mx = v;
#pragma unroll
    for (int o = 16; o > 0; o >>= 1) mx = fmaxf(mx, __shfl_xor_sync(0xffffffffu, mx, o));
    float s = __expf(v - mx);
#pragma unroll
    for (int o = 16; o > 0; o >>= 1) s += __shfl_xor_sync(0xffffffffu, s, o);
    float denom = mx + __logf(s);

    float partial = 0.f;
    int cnt = 0;
    for (int t = lane; t < TT; t += 32) {
        int mt = word[b*TT + t] > 0;
        cnt += mt;
        if (t >= 1 && mt) {
            int tp = label[b*TT + t - 1];
            int tc = label[b*TT + t];
            partial += trans[tp*LL + tc] + emb_[t*LL + tc];
        }
    }
#pragma unroll
    for (int o = 16; o > 0; o >>= 1) {
        partial += __shfl_xor_sync(0xffffffffu, partial, o);
        cnt     += __shfl_xor_sync(0xffffffffu, cnt, o);
    }
    if (lane == 0) {
        int t0 = label[b*TT];
        float num = start_t[t0] + emb_[t0] + partial;
        int last = label[b*TT + cnt - 1];
        num += end_t[last];
        g_llh[b] = num - denom;
    }
}

// ---------------- 5) final reduce ----------------
__global__ void __launch_bounds__(32)
finalize(float* out)
{
    int lane = threadIdx.x;
    float v = g_llh[lane] + g_llh[lane + 32];
#pragma unroll
    for (int o = 16; o > 0; o >>= 1) v += __shfl_xor_sync(0xffffffffu, v, o);
    if (lane == 0) out[0] = -v;
}

// ---------------- host ----------------
extern "C" void kernel_launch(void* const* d_in, const int* in_sizes, int n_in,
                              void* d_out, int out_size)
{
    const int*   word    = (const int*)  d_in[0];
    const int*   label   = (const int*)  d_in[1];
    const float* emb     = (const float*)d_in[2];
    const float* w_ih_l0 = (const float*)d_in[3];
    const float* w_hh_l0 = (const float*)d_in[4];
    const float* b_ih_l0 = (const float*)d_in[5];
    const float* b_hh_l0 = (const float*)d_in[6];
    const float* w_ih_l1 = (const float*)d_in[7];
    const float* w_hh_l1 = (const float*)d_in[8];
    const float* b_ih_l1 = (const float*)d_in[9];
    const float* b_hh_l1 = (const float*)d_in[10];
    const float* w_out   = (const float*)d_in[11];
    const float* b_out   = (const float*)d_in[12];
    const float* start_t = (const float*)d_in[13];
    const float* end_t   = (const float*)d_in[14];
    const float* trans   = (const float*)d_in[15];
    float* out = (float*)d_out;

    cudaFuncSetAttribute(lstm_scan, cudaFuncAttributeMaxDynamicSharedMemorySize, SCAN_SMEM);

    transpose_whh<<<512, 512>>>(w_hh_l0, w_hh_l1);

    gemm_tf32<true ><<<dim3(256, 8), 256>>>(emb, word, w_ih_l0, b_ih_l0, b_hh_l0, DD);
    lstm_scan<<<128, 512, SCAN_SMEM>>>(0);

    gemm_tf32<false><<<dim3(256, 8), 256>>>(nullptr, word, w_ih_l1, b_ih_l1, b_hh_l1, HD2);
    lstm_scan<<<128, 512, SCAN_SMEM>>>(1);

    emission<<<MTOK/8, 256>>>(w_out, b_out);
    crf_kernel<<<BB, 32>>>(word, label, start_t, end_t, trans);
    finalize<<<1, 32>>>(out);
}

// round 5
// speedup vs baseline: 2.0078x; 1.0366x over previous
#include <cuda_runtime.h>
#include <cstddef>
#include <cstdint>

#define BB   64
#define TT   512
#define DD   300
#define HH   128
#define G4   512
#define HD2  256
#define LL   9
#define MTOK (TT*BB)

// ---------------- device scratch ----------------
__device__ float g_xp  [ (size_t)MTOK * 1024 ];  // pre-activations (m, dir*512+g)
__device__ float g_hbuf[ (size_t)MTOK * HD2  ];  // layer output (m, dir*128+j)
__device__ float g_wt  [ 2*2*HH*G4 ];            // [layer][dir][k][g] k-major W_hh
__device__ float g_em  [ (size_t)BB*TT*LL ];     // emissions (b,t,l)
__device__ float g_llh [ BB ];

// ---------------- intrinsics ----------------
__device__ __forceinline__ unsigned long long pack2(float lo, float hi) {
    unsigned long long r;
    asm("mov.b64 %0, {%1, %2};" : "=l"(r) : "f"(lo), "f"(hi));
    return r;
}
__device__ __forceinline__ float2 unpack2(unsigned long long v) {
    float2 f;
    asm("mov.b64 {%0, %1}, %2;" : "=f"(f.x), "=f"(f.y) : "l"(v));
    return f;
}
__device__ __forceinline__ unsigned long long ffma2(unsigned long long a,
                                                    unsigned long long b,
                                                    unsigned long long c) {
    unsigned long long d;
    asm("fma.rn.f32x2 %0, %1, %2, %3;" : "=l"(d) : "l"(a), "l"(b), "l"(c));
    return d;
}
__device__ __forceinline__ float tanh_ap(float x) {
    float y;
    asm("tanh.approx.f32 %0, %1;" : "=f"(y) : "f"(x));
    return y;
}
__device__ __forceinline__ float sig_ap(float x) {
    return fmaf(tanh_ap(0.5f * x), 0.5f, 0.5f);
}
__device__ __forceinline__ uint32_t to_tf32(float f) {
    uint32_t r;
    asm("cvt.rna.tf32.f32 %0, %1;" : "=r"(r) : "f"(f));
    return r;
}
__device__ __forceinline__ void mma_tf32(float* d, const uint32_t* a, uint32_t b0, uint32_t b1) {
    asm("mma.sync.aligned.m16n8k8.row.col.f32.tf32.tf32.f32 "
        "{%0,%1,%2,%3}, {%4,%5,%6,%7}, {%8,%9}, {%0,%1,%2,%3};"
        : "+f"(d[0]), "+f"(d[1]), "+f"(d[2]), "+f"(d[3])
        : "r"(a[0]), "r"(a[1]), "r"(a[2]), "r"(a[3]), "r"(b0), "r"(b1));
}
// pack two f32 into bf16x2 (lo in low 16 bits)
__device__ __forceinline__ uint32_t bf16x2_of(float lo, float hi) {
    uint32_t r;
    asm("cvt.rn.bf16x2.f32 %0, %1, %2;" : "=r"(r) : "f"(hi), "f"(lo));
    return r;
}
// expand bf16x2 -> packed f32x2 (exact: bf16 bits become f32 high halves)
__device__ __forceinline__ unsigned long long bfexp(uint32_t b) {
    uint32_t lo = __byte_perm(b, 0, 0x1044);
    uint32_t hi = __byte_perm(b, 0, 0x3244);
    unsigned long long r;
    asm("mov.b64 %0, {%1, %2};" : "=l"(r) : "r"(lo), "r"(hi));
    return r;
}

// ---------------- 0) W_hh -> k-major ----------------
__global__ void transpose_whh(const float* __restrict__ w0, const float* __restrict__ w1)
{
    int i = blockIdx.x * blockDim.x + threadIdx.x;
    if (i >= 2*2*HH*G4) return;
    int layer = i >> 17;
    int r     = i & 131071;
    int dirr  = r >> 16;
    int r2    = r & 65535;
    int k     = r2 >> 9;
    int g     = r2 & 511;
    const float* w = layer ? w1 : w0;
    g_wt[i] = w[dirr*65536 + g*HH + k];
}

// ---------------- 1) input-projection GEMM (tf32 mma.sync, reg double-buffer) ----------------
template<bool GATHER>
__global__ void __launch_bounds__(256)
gemm_tf32(const float* __restrict__ Asrc, const int* __restrict__ word,
          const float* __restrict__ W, const float* __restrict__ b1,
          const float* __restrict__ b2, int K)
{
    __shared__ uint32_t As[8][132];   // [k][m] tf32 bits
    __shared__ uint32_t Bs[8][132];   // [k][n] tf32 bits
    __shared__ const float* arow_s[128];
    __shared__ float bias_s[128];

    const int tid = threadIdx.x;
    const int m0 = blockIdx.x * 128, n0 = blockIdx.y * 128;

    if (tid < 128) {
        int n = n0 + tid;
        bias_s[tid] = b1[n] + b2[n];
        int m = m0 + tid;
        const float* ap;
        if (GATHER) {
            int b = m & 63, t = m >> 6;
            ap = Asrc + (size_t)word[b*TT + t] * K;
        } else {
            ap = g_hbuf + (size_t)m * K;
        }
        arow_s[tid] = ap;
    }
    __syncthreads();

    const int r  = tid >> 1;
    const int kq = (tid & 1) * 4;
    const float* arow = arow_s[r];
    const float* brow = W + (size_t)(n0 + r) * K;

    const int warp  = tid >> 5;
    const int lane  = tid & 31;
    const int wm    = warp >> 1;
    const int wn    = warp & 1;
    const int group = lane >> 2;
    const int tig   = lane & 3;

    float acc[2][8][4];
#pragma unroll
    for (int mt = 0; mt < 2; mt++)
#pragma unroll
        for (int nt = 0; nt < 8; nt++)
#pragma unroll
            for (int q = 0; q < 4; q++) acc[mt][nt][q] = 0.f;

    // prime k-tile 0
    float4 av = *(const float4*)(arow + kq);
    float4 bv = *(const float4*)(brow + kq);

    for (int k0 = 0; k0 < K; k0 += 8) {
        __syncthreads();   // prior MMA done reading smem
        As[kq+0][r]=to_tf32(av.x); As[kq+1][r]=to_tf32(av.y);
        As[kq+2][r]=to_tf32(av.z); As[kq+3][r]=to_tf32(av.w);
        Bs[kq+0][r]=to_tf32(bv.x); Bs[kq+1][r]=to_tf32(bv.y);
        Bs[kq+2][r]=to_tf32(bv.z); Bs[kq+3][r]=to_tf32(bv.w);

        // prefetch next tile (overlaps with MMA below)
        float4 avn = make_float4(0.f,0.f,0.f,0.f);
        float4 bvn = make_float4(0.f,0.f,0.f,0.f);
        int kn = k0 + 8 + kq;
        if (kn + 4 <= K) {
            avn = *(const float4*)(arow + kn);
            bvn = *(const float4*)(brow + kn);
        }
        __syncthreads();   // smem tile visible

        uint32_t afr[2][4];
#pragma unroll
        for (int mt = 0; mt < 2; mt++) {
            int mr = wm*32 + mt*16 + group;
            afr[mt][0] = As[tig  ][mr];
            afr[mt][1] = As[tig  ][mr + 8];
            afr[mt][2] = As[tig+4][mr];
            afr[mt][3] = As[tig+4][mr + 8];
        }
#pragma unroll
        for (int nt = 0; nt < 8; nt++) {
            int nc = wn*64 + nt*8 + group;
            uint32_t bv0 = Bs[tig  ][nc];
            uint32_t bv1 = Bs[tig+4][nc];
            mma_tf32(acc[0][nt], afr[0], bv0, bv1);
            mma_tf32(acc[1][nt], afr[1], bv0, bv1);
        }
        av = avn; bv = bvn;
    }

#pragma unroll
    for (int mt = 0; mt < 2; mt++) {
        int row = m0 + wm*32 + mt*16 + group;
#pragma unroll
        for (int nt = 0; nt < 8; nt++) {
            int ncl = wn*64 + nt*8 + 2*tig;
            float bc0 = bias_s[ncl], bc1 = bias_s[ncl + 1];
            float* r0 = g_xp + (size_t)row * 1024 + n0 + ncl;
            float* r1 = r0 + (size_t)8 * 1024;
            r0[0] = acc[mt][nt][0] + bc0;  r0[1] = acc[mt][nt][1] + bc1;
            r1[0] = acc[mt][nt][2] + bc0;  r1[1] = acc[mt][nt][3] + bc1;
        }
    }
}

// ---------------- 2) LSTM scan (f32x2 regs + bf16 smem weights) ----------------
// 128 CTAs = (dir, b), 512 threads; thread g owns gate g.
// k 0..95 in 48 f32x2 register pairs; k 96..127 in smem as bf16 uint2[8][512].
#define NREGP 48
#define NSMB  8
#define SCAN_SMEM (NSMB*512*8 + 128*4 + 512*4)

__global__ void __launch_bounds__(512, 1)
lstm_scan(int layer)
{
    extern __shared__ float sm[];
    uint2* wsb = (uint2*)sm;                       // 8*512*8B = 32KB
    float* h_s = (float*)(wsb + NSMB*512);         // 128
    float* gex = h_s + 128;                        // 512

    const int g   = threadIdx.x;
    const int dir = blockIdx.x >> 6;
    const int b   = blockIdx.x & 63;
    const float* pw = g_wt + (size_t)(layer*2 + dir) * 65536;

    unsigned long long wreg[NREGP];
#pragma unroll
    for (int p = 0; p < NREGP; p++)
        wreg[p] = pack2(pw[(2*p)*512 + g], pw[(2*p+1)*512 + g]);

    for (int j = 0; j < NSMB; j++) {
        int kb = 96 + 4*j;
        uint2 v;
        v.x = bf16x2_of(pw[(kb  )*512 + g], pw[(kb+1)*512 + g]);
        v.y = bf16x2_of(pw[(kb+2)*512 + g], pw[(kb+3)*512 + g]);
        wsb[j*512 + g] = v;
    }

    if (g < 128) h_s[g] = 0.f;
    float c = 0.f;
    __syncthreads();

    const float* xpp = g_xp + (size_t)(dir*512 + g);
    int t0 = dir ? (TT - 1) : 0;
    float xcur = xpp[(size_t)(t0*64 + b) * 1024];

    for (int s = 0; s < TT; s++) {
        int t = dir ? (TT - 1 - s) : s;
        int m = t*64 + b;

        float xnext = 0.f;
        if (s + 1 < TT) {
            int tn = dir ? (t - 1) : (t + 1);
            xnext = __ldg(xpp + (size_t)(tn*64 + b) * 1024);
        }

        const ulonglong2* h22 = (const ulonglong2*)h_s;
        unsigned long long acc0 = pack2(xcur, 0.f);
        unsigned long long acc1 = pack2(0.f, 0.f);
#pragma unroll
        for (int j = 0; j < NREGP/2; j++) {          // k 0..95
            ulonglong2 hv = h22[j];
            acc0 = ffma2(hv.x, wreg[2*j],     acc0);
            acc1 = ffma2(hv.y, wreg[2*j + 1], acc1);
        }
#pragma unroll
        for (int j = 0; j < NSMB; j++) {             // k 96..127 (bf16)
            ulonglong2 hv = h22[NREGP/2 + j];
            uint2 wb = wsb[j*512 + g];
            acc0 = ffma2(hv.x, bfexp(wb.x), acc0);
            acc1 = ffma2(hv.y, bfexp(wb.y), acc1);
        }
        float2 s0 = unpack2(acc0);
        float2 s1 = unpack2(acc1);
        gex[g] = (s0.x + s1.x) + (s0.y + s1.y);
        __syncthreads();

        if (g < 128) {
            float i_ = sig_ap(gex[g]);
            float f_ = sig_ap(gex[128 + g]);
            float gg = tanh_ap(gex[256 + g]);
            float o_ = sig_ap(gex[384 + g]);
            c = fmaf(f_, c, i_ * gg);
            float h = o_ * tanh_ap(c);
            h_s[g] = h;
            g_hbuf[(size_t)m * 256 + dir*128 + g] = h;
        }
        __syncthreads();
        xcur = xnext;
    }
}

// ---------------- 3) emission ----------------
__global__ void __launch_bounds__(256)
emission(const float* __restrict__ wout, const float* __restrict__ bout)
{
    __shared__ float ws[LL*256];
    __shared__ float bs[LL];
    int tid = threadIdx.x;
    for (int i = tid; i < LL*256; i += 256) ws[i] = wout[i];
    if (tid < LL) bs[tid] = bout[tid];
    __syncthreads();

    int w = tid >> 5, lane = tid & 31;
    int m = blockIdx.x * 8 + w;
    const float* xr = g_hbuf + (size_t)m * 256;

    float acc[LL];
#pragma unroll
    for (int l = 0; l < LL; l++) acc[l] = 0.f;
#pragma unroll
    for (int q = 0; q < 8; q++) {
        float xv = xr[lane + q*32];
#pragma unroll
        for (int l = 0; l < LL; l++) acc[l] = fmaf(xv, ws[l*256 + lane + q*32], acc[l]);
    }
#pragma unroll
    for (int l = 0; l < LL; l++)
#pragma unroll
        for (int o = 16; o > 0; o >>= 1)
            acc[l] += __shfl_xor_sync(0xffffffffu, acc[l], o);

    if (lane == 0) {
        int t = m >> 6, b = m & 63;
        float* e = g_em + (size_t)b * (TT*LL) + t*LL;
#pragma unroll
        for (int l = 0; l < LL; l++) e[l] = acc[l] + bs[l];
    }
}

// ---------------- 4) CRF ----------------
__global__ void __launch_bounds__(32)
crf_kernel(const int* __restrict__ word, const int* __restrict__ label,
           const float* __restrict__ start_t, const float* __restrict__ end_t,
           const float* __restrict__ trans)
{
    int b = blockIdx.x;
    int lane = threadIdx.x;
    const float* emb_ = g_em + (size_t)b * (TT*LL);

    float tr[LL];
#pragma unroll
    for (int i = 0; i < LL; i++) tr[i] = 0.f;
    if (lane < LL)
#pragma unroll
        for (int i = 0; i < LL; i++) tr[i] = trans[i*LL + lane];

    float alpha = -1e30f;
    if (lane < LL) alpha = start_t[lane] + emb_[lane];

    for (int t = 1; t < TT; t++) {
        bool mt = word[b*TT + t] > 0;
        float emj = (lane < LL) ? emb_[t*LL + lane] : 0.f;
        float vs[LL], mx = -1e30f;
#pragma unroll
        for (int i = 0; i < LL; i++) {
            float ai = __shfl_sync(0xffffffffu, alpha, i);
            vs[i] = ai + tr[i];
            mx = fmaxf(mx, vs[i]);
        }
        float s = 0.f;
#pragma unroll
        for (int i = 0; i < LL; i++) s += __expf(vs[i] - mx);
        float nxt = mx + __logf(s) + emj;
        if (lane < LL && mt) alpha = nxt;
    }

    float v = (lane < LL) ? alpha + end_t[lane] : -1e30f;
    float mx = v;
#pragma unroll
    for (int o = 16; o > 0; o >>= 1) mx = fmaxf(mx, __shfl_xor_sync(0xffffffffu, mx, o));
    float s = __expf(v - mx);
#pragma unroll
    for (int o = 16; o > 0; o >>= 1) s += __shfl_xor_sync(0xffffffffu, s, o);
    float denom = mx + __logf(s);

    float partial = 0.f;
    int cnt = 0;
    for (int t = lane; t < TT; t += 32) {
        int mt = word[b*TT + t] > 0;
        cnt += mt;
        if (t >= 1 && mt) {
            int tp = label[b*TT + t - 1];
            int tc = label[b*TT + t];
            partial += trans[tp*LL + tc] + emb_[t*LL + tc];
        }
    }
#pragma unroll
    for (int o = 16; o > 0; o >>= 1) {
        partial += __shfl_xor_sync(0xffffffffu, partial, o);
        cnt     += __shfl_xor_sync(0xffffffffu, cnt, o);
    }
    if (lane == 0) {
        int t0 = label[b*TT];
        float num = start_t[t0] + emb_[t0] + partial;
        int last = label[b*TT + cnt - 1];
        num += end_t[last];
        g_llh[b] = num - denom;
    }
}

// ---------------- 5) final reduce ----------------
__global__ void __launch_bounds__(32)
finalize(float* out)
{
    int lane = threadIdx.x;
    float v = g_llh[lane] + g_llh[lane + 32];
#pragma unroll
    for (int o = 16; o > 0; o >>= 1) v += __shfl_xor_sync(0xffffffffu, v, o);
    if (lane == 0) out[0] = -v;
}

// ---------------- host ----------------
extern "C" void kernel_launch(void* const* d_in, const int* in_sizes, int n_in,
                              void* d_out, int out_size)
{
    const int*   word    = (const int*)  d_in[0];
    const int*   label   = (const int*)  d_in[1];
    const float* emb     = (const float*)d_in[2];
    const float* w_ih_l0 = (const float*)d_in[3];
    const float* w_hh_l0 = (const float*)d_in[4];
    const float* b_ih_l0 = (const float*)d_in[5];
    const float* b_hh_l0 = (const float*)d_in[6];
    const float* w_ih_l1 = (const float*)d_in[7];
    const float* w_hh_l1 = (const float*)d_in[8];
    const float* b_ih_l1 = (const float*)d_in[9];
    const float* b_hh_l1 = (const float*)d_in[10];
    const float* w_out   = (const float*)d_in[11];
    const float* b_out   = (const float*)d_in[12];
    const float* start_t = (const float*)d_in[13];
    const float* end_t   = (const float*)d_in[14];
    const float* trans   = (const float*)d_in[15];
    float* out = (float*)d_out;

    cudaFuncSetAttribute(lstm_scan, cudaFuncAttributeMaxDynamicSharedMemorySize, SCAN_SMEM);

    transpose_whh<<<512, 512>>>(w_hh_l0, w_hh_l1);

    gemm_tf32<true ><<<dim3(256, 8), 256>>>(emb, word, w_ih_l0, b_ih_l0, b_hh_l0, DD);
    lstm_scan<<<128, 512, SCAN_SMEM>>>(0);

    gemm_tf32<false><<<dim3(256, 8), 256>>>(nullptr, word, w_ih_l1, b_ih_l1, b_hh_l1, HD2);
    lstm_scan<<<128, 512, SCAN_SMEM>>>(1);

    emission<<<MTOK/8, 256>>>(w_out, b_out);
    crf_kernel<<<BB, 32>>>(word, label, start_t, end_t, trans);
    finalize<<<1, 32>>>(out);
}